// round 1
// baseline (speedup 1.0000x reference)
#include <cuda_runtime.h>
#include <math.h>

#define BB 4096
#define TT 128

// ---------------- device scratch (no allocations allowed) ----------------
__device__ float  g_zT[TT * 3 * BB];      // measurements transposed: [t][ch][B]
__device__ float  g_sf[TT * 15 * BB];     // filtered state+cov per step: [t][field][B]
__device__ double g_partial[BB];          // per-sequence loss partials

static __device__ __forceinline__ float sigmoidf(float x) {
    return 1.0f / (1.0f + expf(-x));
}

// ---------------- kernel 1: tiled transpose of measurements ----------------
// in : z[b][t][i]  (B x T x 3, row-major)
// out: g_zT[(t*3+i)*B + b]
__global__ void k_transpose(const float* __restrict__ z) {
    __shared__ float tile[32][33];
    const int k0 = blockIdx.x * 32;   // over T*3 = 384
    const int b0 = blockIdx.y * 32;   // over B
    const int tx = threadIdx.x, ty = threadIdx.y;
#pragma unroll
    for (int j = 0; j < 32; j += 8)
        tile[ty + j][tx] = z[(size_t)(b0 + ty + j) * (TT * 3) + (k0 + tx)];
    __syncthreads();
#pragma unroll
    for (int j = 0; j < 32; j += 8)
        g_zT[(size_t)(k0 + ty + j) * BB + (b0 + tx)] = tile[tx][ty + j];
}

// ---------------- kernel 2: per-sequence EKF forward + RTS backward + loss ----------------
__global__ void __launch_bounds__(32, 1)
k_main(const float* __restrict__ params,
       const float* __restrict__ covp,
       const float* __restrict__ init_states)
{
    const int b = blockIdx.x * blockDim.x + threadIdx.x;
    if (b >= BB) return;

    const float DT      = 1.0f / 120.0f;
    const float TWO_PI  = 6.28318530717958647692f;
    const float FOLD    = 4.71238898038468985769f;   // 1.5*pi

    const float friction = (tanhf(params[0]) + 1.0f) * 0.01f;
    const float damping  = (tanhf(params[1]) + 1.0f) * 0.01f;

    float cp[7];
#pragma unroll
    for (int i = 0; i < 7; i++) cp[i] = sigmoidf(covp[i]);

    const float r[3]  = { cp[0], cp[1], cp[2] };
    const float q0[3] = { cp[3], cp[3], cp[5] };   // position process noise
    const float q1[3] = { cp[4], cp[4], cp[6] };   // velocity process noise
    const float gd    = 1.0f - DT * damping;       // theta-channel velocity gain

    // per-channel state: position p, velocity v, cov (a=P00, bb=P01, c=P11)
    float p[3], v[3], Pa[3], Pb[3], Pc[3];
    p[0] = init_states[b * 6 + 0];
    p[1] = init_states[b * 6 + 1];
    p[2] = init_states[b * 6 + 4];
    v[0] = init_states[b * 6 + 2];
    v[1] = init_states[b * 6 + 3];
    v[2] = init_states[b * 6 + 5];
#pragma unroll
    for (int ch = 0; ch < 3; ch++) { Pa[ch] = 0.01f; Pb[ch] = 0.0f; Pc[ch] = 0.01f; }

    // =========================== FORWARD EKF ===========================
    // prefetch z[t=0]
    float zc[3];
#pragma unroll
    for (int ch = 0; ch < 3; ch++) zc[ch] = g_zT[(size_t)(0 * 3 + ch) * BB + b];

    for (int t = 0; t < TT; t++) {
        float zn[3];
        if (t + 1 < TT) {
#pragma unroll
            for (int ch = 0; ch < 3; ch++)
                zn[ch] = g_zT[(size_t)((t + 1) * 3 + ch) * BB + b];
        }
        float* sf = &g_sf[(size_t)t * 15 * BB + (size_t)b];

#pragma unroll
        for (int ch = 0; ch < 3; ch++) {
            const float vv = v[ch];
            float g, vp;
            if (ch < 2) {
                const float th = tanhf(100.0f * vv);
                vp = vv - DT * (damping * vv + friction * th);
                g  = 1.0f - DT * (damping + friction * 100.0f * (1.0f - th * th));
            } else {
                vp = vv * gd;
                g  = gd;
            }
            const float pp  = p[ch] + DT * vv;
            const float bdc = Pb[ch] + DT * Pc[ch];
            const float ap  = Pa[ch] + DT * Pb[ch] + DT * bdc + q0[ch];
            const float bp  = g * bdc;
            const float cpv = g * g * Pc[ch] + q1[ch];

            float innov = zc[ch] - pp;
            if (ch == 2) innov = innov - TWO_PI * rintf(innov * (1.0f / TWO_PI));

            const float S   = ap + r[ch];
            const float inv = 1.0f / S;
            const float K0  = ap * inv;
            const float K1  = bp * inv;

            p[ch]  = pp + K0 * innov;
            v[ch]  = vp + K1 * innov;
            Pa[ch] = ap  - K0 * ap;
            Pb[ch] = bp  - K0 * bp;
            Pc[ch] = cpv - K1 * bp;

            sf[(size_t)(ch * 2 + 0) * BB]     = p[ch];
            sf[(size_t)(ch * 2 + 1) * BB]     = v[ch];
            sf[(size_t)(6 + ch * 3 + 0) * BB] = Pa[ch];
            sf[(size_t)(6 + ch * 3 + 1) * BB] = Pb[ch];
            sf[(size_t)(6 + ch * 3 + 2) * BB] = Pc[ch];
        }
#pragma unroll
        for (int ch = 0; ch < 3; ch++) zc[ch] = zn[ch];
    }

    double acc = 0.0;

    // loss term at t = T-1 (smoothed == filtered there); zc still holds z[T-1]
    {
        const float Sv0 = Pa[0] + r[0];
        const float Sv1 = Pa[1] + r[1];
        const float Sv2 = Pa[2] + r[2];
        const float e0  = zc[0] - p[0];
        const float e1  = zc[1] - p[1];
        float aA = zc[2] - p[2];
        aA = (aA >  FOLD) ? aA - TWO_PI : aA;
        aA = (aA < -FOLD) ? aA + TWO_PI : aA;
        acc += (double)(Sv0 * Sv1 * Sv2 + Sv0 * e0 * e0 + Sv1 * e1 * e1 + Sv2 * aA * aA);
    }

    // =========================== BACKWARD RTS + LOSS ===========================
    // carry (p,v,Pa,Pb,Pc) currently = filtered at T-1 = (s_next, P_next)

    // prefetch t = T-2 data
    float fp[3], fv[3], fa[3], fb[3], fc[3], zl[3];
    {
        const float* sf = &g_sf[(size_t)(TT - 2) * 15 * BB + (size_t)b];
#pragma unroll
        for (int ch = 0; ch < 3; ch++) {
            fp[ch] = sf[(size_t)(ch * 2 + 0) * BB];
            fv[ch] = sf[(size_t)(ch * 2 + 1) * BB];
            fa[ch] = sf[(size_t)(6 + ch * 3 + 0) * BB];
            fb[ch] = sf[(size_t)(6 + ch * 3 + 1) * BB];
            fc[ch] = sf[(size_t)(6 + ch * 3 + 2) * BB];
            zl[ch] = g_zT[(size_t)((TT - 2) * 3 + ch) * BB + b];
        }
    }

    for (int t = TT - 2; t >= 2; t--) {
        // prefetch next (t-1) while computing current
        float nfp[3], nfv[3], nfa[3], nfb[3], nfc[3], nzl[3];
        if (t > 2) {
            const float* sfn = &g_sf[(size_t)(t - 1) * 15 * BB + (size_t)b];
#pragma unroll
            for (int ch = 0; ch < 3; ch++) {
                nfp[ch] = sfn[(size_t)(ch * 2 + 0) * BB];
                nfv[ch] = sfn[(size_t)(ch * 2 + 1) * BB];
                nfa[ch] = sfn[(size_t)(6 + ch * 3 + 0) * BB];
                nfb[ch] = sfn[(size_t)(6 + ch * 3 + 1) * BB];
                nfc[ch] = sfn[(size_t)(6 + ch * 3 + 2) * BB];
                nzl[ch] = g_zT[(size_t)((t - 1) * 3 + ch) * BB + b];
            }
        }

        float Sv[3], ssp_[3];
#pragma unroll
        for (int ch = 0; ch < 3; ch++) {
            // recompute predicted quantities at t+1 from filtered t
            float g, spv;
            if (ch < 2) {
                const float th = tanhf(100.0f * fv[ch]);
                spv = fv[ch] - DT * (damping * fv[ch] + friction * th);
                g   = 1.0f - DT * (damping + friction * 100.0f * (1.0f - th * th));
            } else {
                spv = fv[ch] * gd;
                g   = gd;
            }
            const float spp = fp[ch] + DT * fv[ch];
            const float bdc = fb[ch] + DT * fc[ch];
            const float ap  = fa[ch] + DT * fb[ch] + DT * bdc + q0[ch];
            const float bp  = g * bdc;
            const float cpv = g * g * fc[ch] + q1[ch];

            const float det  = ap * cpv - bp * bp;
            const float idet = 1.0f / det;

            // G = P_f * F^T * Pp^{-1}
            const float u0 = fa[ch] + DT * fb[ch];
            const float u1 = fb[ch] * g;
            const float w0 = fb[ch] + DT * fc[ch];
            const float w1 = fc[ch] * g;
            const float G00 = (u0 * cpv - u1 * bp) * idet;
            const float G01 = (u1 * ap  - u0 * bp) * idet;
            const float G10 = (w0 * cpv - w1 * bp) * idet;
            const float G11 = (w1 * ap  - w0 * bp) * idet;

            const float ds0 = p[ch] - spp;
            const float ds1 = v[ch] - spv;
            const float ssp = fp[ch] + G00 * ds0 + G01 * ds1;
            const float ssv = fv[ch] + G10 * ds0 + G11 * ds1;

            const float D00 = Pa[ch] - ap;
            const float D01 = Pb[ch] - bp;
            const float D11 = Pc[ch] - cpv;
            const float M00 = G00 * D00 + G01 * D01;
            const float M01 = G00 * D01 + G01 * D11;
            const float M10 = G10 * D00 + G11 * D01;
            const float M11 = G10 * D01 + G11 * D11;

            const float Psa = fa[ch] + M00 * G00 + M01 * G01;
            const float Psb = fb[ch] + M00 * G10 + M01 * G11;
            const float Psc = fc[ch] + M10 * G10 + M11 * G11;

            p[ch]  = ssp;  v[ch]  = ssv;
            Pa[ch] = Psa;  Pb[ch] = Psb;  Pc[ch] = Psc;

            Sv[ch]   = Psa + r[ch];
            ssp_[ch] = ssp;
        }

        // loss term at this t (t >= 2)
        {
            const float e0 = zl[0] - ssp_[0];
            const float e1 = zl[1] - ssp_[1];
            float aA = zl[2] - ssp_[2];
            aA = (aA >  FOLD) ? aA - TWO_PI : aA;
            aA = (aA < -FOLD) ? aA + TWO_PI : aA;
            acc += (double)(Sv[0] * Sv[1] * Sv[2]
                          + Sv[0] * e0 * e0 + Sv[1] * e1 * e1 + Sv[2] * aA * aA);
        }

        if (t > 2) {
#pragma unroll
            for (int ch = 0; ch < 3; ch++) {
                fp[ch] = nfp[ch]; fv[ch] = nfv[ch];
                fa[ch] = nfa[ch]; fb[ch] = nfb[ch]; fc[ch] = nfc[ch];
                zl[ch] = nzl[ch];
            }
        }
    }

    g_partial[b] = acc;
}

// ---------------- kernel 3: deterministic reduction ----------------
__global__ void k_reduce(float* __restrict__ out) {
    __shared__ double sm[1024];
    const int tid = threadIdx.x;
    double s = 0.0;
    for (int i = tid; i < BB; i += 1024) s += g_partial[i];
    sm[tid] = s;
    __syncthreads();
    for (int k = 512; k > 0; k >>= 1) {
        if (tid < k) sm[tid] += sm[tid + k];
        __syncthreads();
    }
    if (tid == 0) out[0] = (float)sm[0];
}

// ---------------- launch ----------------
extern "C" void kernel_launch(void* const* d_in, const int* in_sizes, int n_in,
                              void* d_out, int out_size) {
    const float* params = nullptr;
    const float* covp   = nullptr;
    const float* init   = nullptr;
    const float* meas   = nullptr;

    // robust size-based mapping (sizes are all distinct)
    for (int i = 0; i < n_in; i++) {
        if      (in_sizes[i] == 4)            params = (const float*)d_in[i];
        else if (in_sizes[i] == 7)            covp   = (const float*)d_in[i];
        else if (in_sizes[i] == BB * 6)       init   = (const float*)d_in[i];
        else if (in_sizes[i] == BB * TT * 3)  meas   = (const float*)d_in[i];
    }
    // positional fallback
    if (!params && n_in > 0) params = (const float*)d_in[0];
    if (!covp   && n_in > 1) covp   = (const float*)d_in[1];
    if (!init   && n_in > 2) init   = (const float*)d_in[2];
    if (!meas   && n_in > 3) meas   = (const float*)d_in[3];

    dim3 tb(32, 8);
    dim3 tg((TT * 3) / 32, BB / 32);
    k_transpose<<<tg, tb>>>(meas);

    k_main<<<BB / 32, 32>>>(params, covp, init);

    k_reduce<<<1, 1024>>>((float*)d_out);
}

// round 2
// speedup vs baseline: 1.7867x; 1.7867x over previous
#include <cuda_runtime.h>
#include <math.h>

#define BB 4096
#define TT 128

// ---------------- device scratch ----------------
__device__ float  g_zT[TT * 3 * BB];       // measurements transposed: [t*3+ch][B]
__device__ float4 g_sf4[TT * 4 * BB];      // packed filtered state+cov: [t][4][B]
__device__ float  g_partial[BB];           // per-sequence loss partials

static __device__ __forceinline__ float sigmoidf(float x) {
    return 1.0f / (1.0f + expf(-x));
}
static __device__ __forceinline__ float tanh_fast(float x) {
    float y; asm("tanh.approx.f32 %0, %1;" : "=f"(y) : "f"(x)); return y;
}
static __device__ __forceinline__ float rcp_fast(float x) {
    float y; asm("rcp.approx.f32 %0, %1;" : "=f"(y) : "f"(x));
    return y * __fmaf_rn(-x, y, 2.0f);   // one Newton step
}

// ---------------- kernel 1: tiled transpose of measurements ----------------
__global__ void k_transpose(const float* __restrict__ z) {
    __shared__ float tile[32][33];
    const int k0 = blockIdx.x * 32;   // over T*3 = 384
    const int b0 = blockIdx.y * 32;   // over B
    const int tx = threadIdx.x, ty = threadIdx.y;
#pragma unroll
    for (int j = 0; j < 32; j += 8)
        tile[ty + j][tx] = z[(size_t)(b0 + ty + j) * (TT * 3) + (k0 + tx)];
    __syncthreads();
#pragma unroll
    for (int j = 0; j < 32; j += 8)
        g_zT[(size_t)(k0 + ty + j) * BB + (b0 + tx)] = tile[tx][ty + j];
}

// ---------------- backward slot ----------------
struct Slot {
    float4 a, b, c, d;
    float z0, z1, z2;
};
static __device__ __forceinline__ void load_slot(Slot& s, int t, int b) {
    const float4* gs = g_sf4 + (size_t)t * 4 * BB + b;
    s.a = gs[0];
    s.b = gs[BB];
    s.c = gs[2 * BB];
    s.d = gs[3 * BB];
    s.z0 = g_zT[(size_t)(t * 3 + 0) * BB + b];
    s.z1 = g_zT[(size_t)(t * 3 + 1) * BB + b];
    s.z2 = g_zT[(size_t)(t * 3 + 2) * BB + b];
}

// one backward RTS + loss step (consumes filtered data at time t, carry = smoothed at t+1)
static __device__ __forceinline__ void bw_step(
    const float4 c0, const float4 c1, const float4 c2, const float4 c3,
    const float zl0, const float zl1, const float zl2,
    float* p, float* v, float* Pa, float* Pb, float* Pc,
    const float damping, const float friction, const float gd,
    const float* r, const float* qp, const float* qv,
    float& acc)
{
    const float DT     = 1.0f / 120.0f;
    const float TWO_PI = 6.28318530717958647692f;
    const float FOLD   = 4.71238898038468985769f;

    float fp[3], fv[3], fa[3], fb[3], fc[3];
    fp[0] = c0.x; fv[0] = c0.y; fp[1] = c0.z; fv[1] = c0.w;
    fp[2] = c1.x; fv[2] = c1.y; fa[0] = c1.z; fb[0] = c1.w;
    fc[0] = c2.x; fa[1] = c2.y; fb[1] = c2.z; fc[1] = c2.w;
    fa[2] = c3.x; fb[2] = c3.y; fc[2] = c3.z;

    float Sv[3], ssp_[3];
#pragma unroll
    for (int ch = 0; ch < 3; ch++) {
        float g, spv;
        if (ch < 2) {
            const float th = tanh_fast(100.0f * fv[ch]);
            spv = fv[ch] - DT * (damping * fv[ch] + friction * th);
            g   = 1.0f - DT * (damping + friction * 100.0f * (1.0f - th * th));
        } else {
            spv = fv[ch] * gd;
            g   = gd;
        }
        const float spp = fp[ch] + DT * fv[ch];
        const float bdc = fb[ch] + DT * fc[ch];
        const float ap  = fa[ch] + DT * fb[ch] + DT * bdc + qp[ch];
        const float bp  = g * bdc;
        const float cpv = g * g * fc[ch] + qv[ch];

        const float idet = rcp_fast(ap * cpv - bp * bp);

        const float u0 = fa[ch] + DT * fb[ch];
        const float u1 = fb[ch] * g;
        const float w0 = fb[ch] + DT * fc[ch];
        const float w1 = fc[ch] * g;
        const float G00 = (u0 * cpv - u1 * bp) * idet;
        const float G01 = (u1 * ap  - u0 * bp) * idet;
        const float G10 = (w0 * cpv - w1 * bp) * idet;
        const float G11 = (w1 * ap  - w0 * bp) * idet;

        const float ds0 = p[ch] - spp;
        const float ds1 = v[ch] - spv;
        const float ssp = fp[ch] + G00 * ds0 + G01 * ds1;
        const float ssv = fv[ch] + G10 * ds0 + G11 * ds1;

        const float D00 = Pa[ch] - ap;
        const float D01 = Pb[ch] - bp;
        const float D11 = Pc[ch] - cpv;
        const float M00 = G00 * D00 + G01 * D01;
        const float M01 = G00 * D01 + G01 * D11;
        const float M10 = G10 * D00 + G11 * D01;
        const float M11 = G10 * D01 + G11 * D11;

        const float Psa = fa[ch] + M00 * G00 + M01 * G01;
        const float Psb = fb[ch] + M00 * G10 + M01 * G11;
        const float Psc = fc[ch] + M10 * G10 + M11 * G11;

        p[ch]  = ssp;  v[ch]  = ssv;
        Pa[ch] = Psa;  Pb[ch] = Psb;  Pc[ch] = Psc;

        Sv[ch]   = Psa + r[ch];
        ssp_[ch] = ssp;
    }

    const float e0 = zl0 - ssp_[0];
    const float e1 = zl1 - ssp_[1];
    float aA = zl2 - ssp_[2];
    aA = (aA >  FOLD) ? aA - TWO_PI : aA;
    aA = (aA < -FOLD) ? aA + TWO_PI : aA;
    acc += Sv[0] * Sv[1] * Sv[2]
         + Sv[0] * e0 * e0 + Sv[1] * e1 * e1 + Sv[2] * aA * aA;
}

// ---------------- kernel 2: EKF forward + RTS backward + loss ----------------
__global__ void __launch_bounds__(32, 1)
k_main(const float* __restrict__ params,
       const float* __restrict__ covp,
       const float* __restrict__ init_states)
{
    const int b = blockIdx.x * blockDim.x + threadIdx.x;
    if (b >= BB) return;

    const float DT      = 1.0f / 120.0f;
    const float TWO_PI  = 6.28318530717958647692f;
    const float INV2PI  = 0.15915494309189533577f;
    const float FOLD    = 4.71238898038468985769f;

    const float friction = (tanhf(params[0]) + 1.0f) * 0.01f;
    const float damping  = (tanhf(params[1]) + 1.0f) * 0.01f;

    float cp[7];
#pragma unroll
    for (int i = 0; i < 7; i++) cp[i] = sigmoidf(covp[i]);

    const float r[3]  = { cp[0], cp[1], cp[2] };
    const float qp[3] = { cp[3], cp[3], cp[5] };
    const float qv[3] = { cp[4], cp[4], cp[6] };
    const float gd    = 1.0f - DT * damping;

    float p[3], v[3], Pa[3], Pb[3], Pc[3];
    p[0] = init_states[b * 6 + 0];
    p[1] = init_states[b * 6 + 1];
    p[2] = init_states[b * 6 + 4];
    v[0] = init_states[b * 6 + 2];
    v[1] = init_states[b * 6 + 3];
    v[2] = init_states[b * 6 + 5];
#pragma unroll
    for (int ch = 0; ch < 3; ch++) { Pa[ch] = 0.01f; Pb[ch] = 0.0f; Pc[ch] = 0.01f; }

    // =========================== FORWARD EKF ===========================
    float zb[4][3];
#pragma unroll
    for (int j = 0; j < 4; j++)
#pragma unroll
        for (int ch = 0; ch < 3; ch++)
            zb[j][ch] = g_zT[(size_t)(j * 3 + ch) * BB + b];

    for (int tb = 0; tb < TT; tb += 4) {
#pragma unroll
        for (int j = 0; j < 4; j++) {
            const int t = tb + j;
            float zc[3];
#pragma unroll
            for (int ch = 0; ch < 3; ch++) zc[ch] = zb[j][ch];
            // prefetch t+4 (overwrites this slot)
            if (t + 4 < TT) {
#pragma unroll
                for (int ch = 0; ch < 3; ch++)
                    zb[j][ch] = g_zT[(size_t)((t + 4) * 3 + ch) * BB + b];
            }

#pragma unroll
            for (int ch = 0; ch < 3; ch++) {
                const float vv = v[ch];
                float g, vp;
                if (ch < 2) {
                    const float th = tanh_fast(100.0f * vv);
                    vp = vv - DT * (damping * vv + friction * th);
                    g  = 1.0f - DT * (damping + friction * 100.0f * (1.0f - th * th));
                } else {
                    vp = vv * gd;
                    g  = gd;
                }
                const float pp  = p[ch] + DT * vv;
                const float bdc = Pb[ch] + DT * Pc[ch];
                const float ap  = Pa[ch] + DT * Pb[ch] + DT * bdc + qp[ch];
                const float bp  = g * bdc;
                const float cpv = g * g * Pc[ch] + qv[ch];

                float innov = zc[ch] - pp;
                if (ch == 2) innov = innov - TWO_PI * rintf(innov * INV2PI);

                const float inv = rcp_fast(ap + r[ch]);
                const float K0  = ap * inv;
                const float K1  = bp * inv;

                p[ch]  = pp + K0 * innov;
                v[ch]  = vp + K1 * innov;
                Pa[ch] = ap  - K0 * ap;
                Pb[ch] = bp  - K0 * bp;
                Pc[ch] = cpv - K1 * bp;
            }

            float4* gs = g_sf4 + (size_t)t * 4 * BB + b;
            gs[0]      = make_float4(p[0], v[0], p[1], v[1]);
            gs[BB]     = make_float4(p[2], v[2], Pa[0], Pb[0]);
            gs[2 * BB] = make_float4(Pc[0], Pa[1], Pb[1], Pc[1]);
            gs[3 * BB] = make_float4(Pa[2], Pb[2], Pc[2], 0.0f);
        }
    }

    float acc = 0.0f;

    // loss term at t = T-1 (smoothed == filtered)
    {
        float zf[3];
#pragma unroll
        for (int ch = 0; ch < 3; ch++)
            zf[ch] = g_zT[(size_t)((TT - 1) * 3 + ch) * BB + b];
        const float Sv0 = Pa[0] + r[0];
        const float Sv1 = Pa[1] + r[1];
        const float Sv2 = Pa[2] + r[2];
        const float e0  = zf[0] - p[0];
        const float e1  = zf[1] - p[1];
        float aA = zf[2] - p[2];
        aA = (aA >  FOLD) ? aA - TWO_PI : aA;
        aA = (aA < -FOLD) ? aA + TWO_PI : aA;
        acc += Sv0 * Sv1 * Sv2 + Sv0 * e0 * e0 + Sv1 * e1 * e1 + Sv2 * aA * aA;
    }

    // =========================== BACKWARD RTS + LOSS ===========================
    Slot A, B;
    load_slot(A, TT - 2, b);
    load_slot(B, TT - 3, b);

    int t = TT - 2;
    for (;;) {
        {
            const float4 c0 = A.a, c1 = A.b, c2 = A.c, c3 = A.d;
            const float z0 = A.z0, z1 = A.z1, z2 = A.z2;
            if (t - 2 >= 2) load_slot(A, t - 2, b);
            bw_step(c0, c1, c2, c3, z0, z1, z2,
                    p, v, Pa, Pb, Pc, damping, friction, gd, r, qp, qv, acc);
            if (--t < 2) break;
        }
        {
            const float4 c0 = B.a, c1 = B.b, c2 = B.c, c3 = B.d;
            const float z0 = B.z0, z1 = B.z1, z2 = B.z2;
            if (t - 2 >= 2) load_slot(B, t - 2, b);
            bw_step(c0, c1, c2, c3, z0, z1, z2,
                    p, v, Pa, Pb, Pc, damping, friction, gd, r, qp, qv, acc);
            if (--t < 2) break;
        }
    }

    g_partial[b] = acc;
}

// ---------------- kernel 3: deterministic reduction ----------------
__global__ void k_reduce(float* __restrict__ out) {
    __shared__ double sm[1024];
    const int tid = threadIdx.x;
    double s = 0.0;
    for (int i = tid; i < BB; i += 1024) s += (double)g_partial[i];
    sm[tid] = s;
    __syncthreads();
    for (int k = 512; k > 0; k >>= 1) {
        if (tid < k) sm[tid] += sm[tid + k];
        __syncthreads();
    }
    if (tid == 0) out[0] = (float)sm[0];
}

// ---------------- launch ----------------
extern "C" void kernel_launch(void* const* d_in, const int* in_sizes, int n_in,
                              void* d_out, int out_size) {
    const float* params = nullptr;
    const float* covp   = nullptr;
    const float* init   = nullptr;
    const float* meas   = nullptr;

    for (int i = 0; i < n_in; i++) {
        if      (in_sizes[i] == 4)            params = (const float*)d_in[i];
        else if (in_sizes[i] == 7)            covp   = (const float*)d_in[i];
        else if (in_sizes[i] == BB * 6)       init   = (const float*)d_in[i];
        else if (in_sizes[i] == BB * TT * 3)  meas   = (const float*)d_in[i];
    }
    if (!params && n_in > 0) params = (const float*)d_in[0];
    if (!covp   && n_in > 1) covp   = (const float*)d_in[1];
    if (!init   && n_in > 2) init   = (const float*)d_in[2];
    if (!meas   && n_in > 3) meas   = (const float*)d_in[3];

    dim3 tb(32, 8);
    dim3 tg((TT * 3) / 32, BB / 32);
    k_transpose<<<tg, tb>>>(meas);

    k_main<<<BB / 32, 32>>>(params, covp, init);

    k_reduce<<<1, 1024>>>((float*)d_out);
}